// round 14
// baseline (speedup 1.0000x reference)
#include <cuda_runtime.h>
#include <cstdint>

// Per-token int4 quantization — 256-bit memory ops (sm_103 native v8.b32):
//   x: [N, H] fp32 (H = 4096)
//   scales[n] = max|x[n,:]| / 7
//   q = rint(x * 7/max)   (in [-7,7] by construction; clamp-free)
//   packed byte = ((q_odd & 0xF) << 4) | (q_even & 0xF)  (signed int8 value)
//
// Per thread: 2x LDG.256 (lane-consecutive 32B chunks -> 1KB/warp/instr)
// and 2x STG.128 (FLOAT_OUT) / 2x STG.32 (BYTE_OUT). Half the memory
// instructions of the LDG.128 version; same coalescing.
//
// Cache policy: loads streaming (.cs); stores default write-back (graph
// replays overwrite d_out -> L2-resident dirty lines never hit DRAM).
//
// Harness output layout (detected via out_size):
//   FLOAT_OUT: [N*H/2 float32 (packed byte values)][N float32 scales]
//   BYTE_OUT : [N*H/2 int8][N float32 scales]

constexpr int H       = 4096;
constexpr int THREADS = 256;
constexpr int VLOADS  = H / 8 / THREADS;  // 2 v8-loads per thread

struct f8 { float v[8]; };

__device__ __forceinline__ f8 ldg256_cs(const float* p)
{
    f8 r;
    asm volatile("ld.global.cs.v8.f32 {%0,%1,%2,%3,%4,%5,%6,%7}, [%8];"
                 : "=f"(r.v[0]), "=f"(r.v[1]), "=f"(r.v[2]), "=f"(r.v[3]),
                   "=f"(r.v[4]), "=f"(r.v[5]), "=f"(r.v[6]), "=f"(r.v[7])
                 : "l"(p));
    return r;
}

template <bool FLOAT_OUT>
__global__ __launch_bounds__(THREADS, 8)
void quant_int4_kernel(const float* __restrict__ x,
                       void* __restrict__ packed_out,
                       float* __restrict__ scales)
{
    const int row = blockIdx.x;
    const int t   = threadIdx.x;

    const float* xr = x + (size_t)row * H;

    // 2 front-batched 256-bit streaming loads, lane-consecutive.
    f8 v[VLOADS];
#pragma unroll
    for (int k = 0; k < VLOADS; ++k)
        v[k] = ldg256_cs(xr + 8 * (t + THREADS * k));

    // Local max|x|
    float m = 0.0f;
#pragma unroll
    for (int k = 0; k < VLOADS; ++k)
#pragma unroll
        for (int i = 0; i < 8; ++i)
            m = fmaxf(m, fabsf(v[k].v[i]));

    // Warp reduce
#pragma unroll
    for (int o = 16; o > 0; o >>= 1)
        m = fmaxf(m, __shfl_xor_sync(0xffffffffu, m, o));

    __shared__ float smax[THREADS / 32];
    if ((t & 31) == 0) smax[t >> 5] = m;
    __syncthreads();

    float rowmax = smax[0];
#pragma unroll
    for (int w = 1; w < THREADS / 32; ++w)
        rowmax = fmaxf(rowmax, smax[w]);

    const float scale = rowmax / 7.0f;                        // exact fp32
    const float inv   = (rowmax > 0.0f) ? 7.0f / rowmax : 0.0f;

    if (t == 0) scales[row] = scale;

    // Quantize: 8 floats -> 4 packed byte values per v8 load. Clamp-free.
    if (FLOAT_OUT) {
        float4* op = reinterpret_cast<float4*>((float*)packed_out + (size_t)row * (H / 2));
#pragma unroll
        for (int k = 0; k < VLOADS; ++k) {
            float b[4];
#pragma unroll
            for (int i = 0; i < 4; ++i) {
                // rintf == FRND round-half-even, matches reference rounding.
                float q0 = rintf(v[k].v[2 * i + 0] * inv);
                float q1 = rintf(v[k].v[2 * i + 1] * inv);
                // low-nibble value: q + 16 if q < 0 (maps [-8,-1] -> [8,15])
                float n0 = q0 + (q0 < 0.0f ? 16.0f : 0.0f);
                b[i] = fmaf(16.0f, q1, n0);   // exact: small integers
            }
            op[t + THREADS * k] = make_float4(b[0], b[1], b[2], b[3]);
        }
    } else {
        uint32_t* op = reinterpret_cast<uint32_t*>((int8_t*)packed_out + (size_t)row * (H / 2));
#pragma unroll
        for (int k = 0; k < VLOADS; ++k) {
            uint32_t w = 0;
#pragma unroll
            for (int i = 0; i < 4; ++i) {
                int q0 = __float2int_rn(v[k].v[2 * i + 0] * inv);
                int q1 = __float2int_rn(v[k].v[2 * i + 1] * inv);
                w |= (uint32_t)((((q1 & 0xF) << 4) | (q0 & 0xF)) & 0xFF) << (8 * i);
            }
            op[t + THREADS * k] = w;
        }
    }
}

extern "C" void kernel_launch(void* const* d_in, const int* in_sizes, int n_in,
                              void* d_out, int out_size)
{
    const float* x = (const float*)d_in[0];
    const int rows = in_sizes[0] / H;
    const long long packed_elems = (long long)rows * (H / 2);

    if ((long long)out_size == packed_elems + rows) {
        // float32 layout: packed values as floats, then scales
        float* packed = (float*)d_out;
        float* scales = packed + packed_elems;
        quant_int4_kernel<true><<<rows, THREADS>>>(x, packed, scales);
    } else {
        // int8 layout: packed bytes, then fp32 scales appended as raw bytes
        int8_t* packed = (int8_t*)d_out;
        float*  scales = (float*)(packed + packed_elems);
        quant_int4_kernel<false><<<rows, THREADS>>>(x, packed, scales);
    }
}